// round 5
// baseline (speedup 1.0000x reference)
#include <cuda_runtime.h>
#include <cstdint>

#define DEVFN __device__ __forceinline__

constexpr int BN = 16;      // batch
constexpr int CI = 64;      // in channels
constexpr int CO = 64;      // out channels
constexpr int HW = 4096;    // 64x64
constexpr int OC = 18;      // offset channels (2*K*K)
constexpr int OSTR = 20;    // g_off row stride (floats)

// Scratch (static device memory)
__device__ __align__(16) float g_xt [BN * HW * CI];       // x in NHWC
__device__ __align__(16) float g_off[BN * HW * OSTR];     // offsets [pixel][20]
__device__ __align__(16) float g_wt2[9 * CI * CO * 2];    // [(t*64+k)*128 + co*2 + d] duplicated
__device__ __align__(16) float g_wo2[9 * CI * OC * 2];    // [(t*64+k)*36  + oc*2 + d] duplicated

DEVFN void fma2(unsigned long long& d, unsigned long long a, unsigned long long b) {
    asm("fma.rn.f32x2 %0, %1, %2, %0;" : "+l"(d) : "l"(a), "l"(b));
}
union F4U { float4 f; unsigned long long u[2]; };

// ---------------------------------------------------------------------------
// Weight prepack with duplication: every weight stored as {w, w}.
// ---------------------------------------------------------------------------
__global__ void k_prepack(const float* __restrict__ wdcn, const float* __restrict__ woff) {
    int i = blockIdx.x * blockDim.x + threadIdx.x;
    if (i < 9 * CI * CO * 2) {
        int co = (i >> 1) & 63;
        int k  = (i >> 7) & 63;
        int t  = i >> 13;
        g_wt2[i] = wdcn[(co * CI + k) * 9 + t];
    }
    int j = i - 9 * CI * CO * 2;
    if (j >= 0 && j < 9 * CI * OC * 2) {
        int r  = j >> 1;
        int oc = r % OC;
        int rk = r / OC;
        int k  = rk & 63;
        int t  = rk >> 6;
        g_wo2[j] = woff[(oc * CI + k) * 9 + t];
    }
}

// ---------------------------------------------------------------------------
// NCHW -> NHWC transpose
// ---------------------------------------------------------------------------
__global__ void k_transpose(const float* __restrict__ x) {
    __shared__ float s[32][33];
    int b  = blockIdx.z;
    int c0 = blockIdx.y * 32;
    int p0 = blockIdx.x * 32;
    int tx = threadIdx.x, ty = threadIdx.y;   // 32 x 8
    const float* xb = x + (size_t)b * CI * HW;
#pragma unroll
    for (int i = 0; i < 4; i++)
        s[ty + 8 * i][tx] = xb[(size_t)(c0 + ty + 8 * i) * HW + p0 + tx];
    __syncthreads();
    float* xtb = g_xt + (size_t)b * HW * CI;
#pragma unroll
    for (int i = 0; i < 4; i++)
        xtb[(size_t)(p0 + ty + 8 * i) * CI + c0 + tx] = s[tx][ty + 8 * i];
}

// Pair-major swizzled im2col cell: float4 = {v(2k2,p), v(2k2,p+1), v(2k2+1,p), v(2k2+1,p+1)}
// at colv[p2*32 + (k2 ^ ((p2>>2)&7))].  Store phase: lanes vary k2 -> distinct banks.
// GEMM phase: lanes vary p2 (p2 = gpx*4+j, sw = gpx) -> distinct banks.

// ---------------------------------------------------------------------------
// Offset conv: 3x3, 64->18. Tile = 64 px (one row), 128 threads, grid 1024.
// ---------------------------------------------------------------------------
__global__ __launch_bounds__(128, 6) void k_offconv(const float* __restrict__ boff) {
    __shared__ __align__(16) float4 colv[32 * 32];    // 16 KB
    int tid  = threadIdx.x;
    int base = blockIdx.x * 64;
    int b    = base >> 12;
    int prow = base & 4095;
    int ho   = prow >> 6;                // this tile = one image row
    const float* xtb = g_xt + (size_t)b * HW * CI;
    int lane = tid & 31, wrp = tid >> 5; // lane = k2 (channel pair)
    int gco = tid >> 3, gpx = tid & 7;   // gemm mapping (active tid < 72)

    F4U acc[2];
#pragma unroll
    for (int i = 0; i < 2; i++) { acc[i].u[0] = acc[i].u[1] = 0ULL; }
    unsigned long long acc2[2][2] = {{0, 0}, {0, 0}};  // pairs j=2,3
    // acc layout: acc[i].u[j] for j=0,1 ; acc2[i][j-2] for j=2,3

    const float4* w4 = (const float4*)g_wo2;

    for (int t = 0; t < 9; t++) {
        int dy = t / 3 - 1;
        int dx = t - (t / 3) * 3 - 1;
        int y  = ho + dy;
        bool yok = ((unsigned)y < 64u);
        // ---- gather: 8 cells/thread (p2 = wrp*8+it), each = 2ch x 2px ----
#pragma unroll
        for (int it = 0; it < 8; it++) {
            int p2 = wrp * 8 + it;
            int q0 = 2 * p2;
            int x0p = q0 + dx, x1p = x0p + 1;
            float2 a = make_float2(0.f, 0.f), bb = make_float2(0.f, 0.f);
            if (yok && (unsigned)x0p < 64u)
                a = *((const float2*)(xtb + (((y << 6) + x0p) << 6)) + lane);
            if (yok && (unsigned)x1p < 64u)
                bb = *((const float2*)(xtb + (((y << 6) + x1p) << 6)) + lane);
            colv[p2 * 32 + (lane ^ ((p2 >> 2) & 7))] = make_float4(a.x, bb.x, a.y, bb.y);
        }
        __syncthreads();
        if (tid < 72) {
#pragma unroll 2
            for (int k2 = 0; k2 < 32; k2++) {
                F4U wa, wb;
                wa.f = w4[(t * 64 + 2 * k2) * 9 + gco];       // k even: {w(2gco)dup, w(2gco+1)dup}
                wb.f = w4[(t * 64 + 2 * k2 + 1) * 9 + gco];   // k odd
#pragma unroll
                for (int j = 0; j < 4; j++) {
                    F4U cv; cv.f = colv[(gpx * 4 + j) * 32 + (k2 ^ gpx)];
                    unsigned long long* a0 = (j < 2) ? &acc[0].u[j] : &acc2[0][j - 2];
                    unsigned long long* a1 = (j < 2) ? &acc[1].u[j] : &acc2[1][j - 2];
                    fma2(*a0, wa.u[0], cv.u[0]); fma2(*a0, wb.u[0], cv.u[1]);
                    fma2(*a1, wa.u[1], cv.u[0]); fma2(*a1, wb.u[1], cv.u[1]);
                }
            }
        }
        __syncthreads();
    }
    if (tid < 72) {
        int co0 = 2 * gco;
#pragma unroll
        for (int i = 0; i < 2; i++) {
            float bo = boff[co0 + i];
            float r[8];
            r[0] = ((float2*)&acc[i].u[0])->x;  r[1] = ((float2*)&acc[i].u[0])->y;
            r[2] = ((float2*)&acc[i].u[1])->x;  r[3] = ((float2*)&acc[i].u[1])->y;
            r[4] = ((float2*)&acc2[i][0])->x;   r[5] = ((float2*)&acc2[i][0])->y;
            r[6] = ((float2*)&acc2[i][1])->x;   r[7] = ((float2*)&acc2[i][1])->y;
#pragma unroll
            for (int m = 0; m < 8; m++)
                g_off[(size_t)(base + gpx * 8 + m) * OSTR + co0 + i] = r[m] + bo;
        }
    }
}

// ---------------------------------------------------------------------------
// Deformable conv. Tile = 64 px (one row) x 64 co, 128 threads, grid 1024.
// Thread tile 4co x 8px. Weights via duplicated-gmem LDG.128 (zero pack MOVs).
// ---------------------------------------------------------------------------
__global__ __launch_bounds__(128, 5) void k_deform(const float* __restrict__ bdcn,
                                                   float* __restrict__ out) {
    __shared__ __align__(16) float4 colv[32 * 32];    // 16 KB
    int tid  = threadIdx.x;
    int base = blockIdx.x * 64;
    int b    = base >> 12;
    int prow = base & 4095;
    int ho   = prow >> 6;
    const float* xtb = g_xt + (size_t)b * HW * CI;
    int lane = tid & 31, wrp = tid >> 5;
    int gco = tid >> 3, gpx = tid & 7;
    int co0 = 4 * gco;

    F4U acc[4];
#pragma unroll
    for (int i = 0; i < 4; i++) { acc[i].u[0] = acc[i].u[1] = 0ULL; acc[i].f = make_float4(0,0,0,0); }
    unsigned long long accA[4][4];
#pragma unroll
    for (int i = 0; i < 4; i++)
#pragma unroll
        for (int j = 0; j < 4; j++) accA[i][j] = 0ULL;

    const float4* w4 = (const float4*)g_wt2;
    float fho = (float)ho;

    for (int t = 0; t < 9; t++) {
        float dy = (float)(t / 3 - 1);
        float dx = (float)(t - (t / 3) * 3 - 1);
        // ---- bilinear gather: 8 cells/thread, each = 2ch x 2px ----
#pragma unroll 2
        for (int it = 0; it < 8; it++) {
            int p2 = wrp * 8 + it;
            int q0 = 2 * p2;
            const float* ob = g_off + (size_t)(base + q0) * OSTR + 2 * t;
            float2 o0 = *(const float2*)ob;
            float2 o1 = *(const float2*)(ob + OSTR);
            float2 r[2];
#pragma unroll
            for (int s = 0; s < 2; s++) {
                float2 o = s ? o1 : o0;
                float py  = fho + dy + o.x;
                float pxx = (float)(q0 + s) + dx + o.y;
                float y0f = floorf(py), x0f = floorf(pxx);
                float fy = py - y0f, fx = pxx - x0f;
                int y0 = (int)y0f, x0 = (int)x0f;
                float vy0 = ((unsigned)y0 < 64u) ? 1.f : 0.f;
                float vy1 = ((unsigned)(y0 + 1) < 64u) ? 1.f : 0.f;
                float vx0 = ((unsigned)x0 < 64u) ? 1.f : 0.f;
                float vx1 = ((unsigned)(x0 + 1) < 64u) ? 1.f : 0.f;
                float gy0 = 1.f - fy, gx0 = 1.f - fx;
                float w00 = gy0 * gx0 * vy0 * vx0;
                float w01 = gy0 * fx  * vy0 * vx1;
                float w10 = fy  * gx0 * vy1 * vx0;
                float w11 = fy  * fx  * vy1 * vx1;
                int yc0 = min(max(y0, 0), 63),     yc1 = min(max(y0 + 1, 0), 63);
                int xc0 = min(max(x0, 0), 63),     xc1 = min(max(x0 + 1, 0), 63);
                float2 v00 = *((const float2*)(xtb + (((yc0 << 6) + xc0) << 6)) + lane);
                float2 v01 = *((const float2*)(xtb + (((yc0 << 6) + xc1) << 6)) + lane);
                float2 v10 = *((const float2*)(xtb + (((yc1 << 6) + xc0) << 6)) + lane);
                float2 v11 = *((const float2*)(xtb + (((yc1 << 6) + xc1) << 6)) + lane);
                r[s].x = w00 * v00.x + w01 * v01.x + w10 * v10.x + w11 * v11.x;
                r[s].y = w00 * v00.y + w01 * v01.y + w10 * v10.y + w11 * v11.y;
            }
            colv[p2 * 32 + (lane ^ ((p2 >> 2) & 7))] = make_float4(r[0].x, r[1].x, r[0].y, r[1].y);
        }
        __syncthreads();
        // ---- GEMM over this tap's 64 cin (as 32 channel-pairs) ----
        {
            int wbase = (t * 64) * 32 + 2 * gco;
#pragma unroll 2
            for (int k2 = 0; k2 < 32; k2++) {
                F4U wA, wB, wC, wD;
                wA.f = w4[wbase + (2 * k2) * 32];          // co0,co0+1  (k = 2k2)
                wB.f = w4[wbase + (2 * k2) * 32 + 1];      // co0+2,co0+3
                wC.f = w4[wbase + (2 * k2 + 1) * 32];      // co0,co0+1  (k = 2k2+1)
                wD.f = w4[wbase + (2 * k2 + 1) * 32 + 1];
#pragma unroll
                for (int j = 0; j < 4; j++) {
                    F4U cv; cv.f = colv[(gpx * 4 + j) * 32 + (k2 ^ gpx)];
                    fma2(accA[0][j], wA.u[0], cv.u[0]); fma2(accA[0][j], wC.u[0], cv.u[1]);
                    fma2(accA[1][j], wA.u[1], cv.u[0]); fma2(accA[1][j], wC.u[1], cv.u[1]);
                    fma2(accA[2][j], wB.u[0], cv.u[0]); fma2(accA[2][j], wD.u[0], cv.u[1]);
                    fma2(accA[3][j], wB.u[1], cv.u[0]); fma2(accA[3][j], wD.u[1], cv.u[1]);
                }
            }
        }
        __syncthreads();
    }
    // ---- epilogue: out[b][co][row][px] (NCHW) ----
#pragma unroll
    for (int i = 0; i < 4; i++) {
        int co = co0 + i;
        float bias = bdcn[co];
        float2 p0 = *(float2*)&accA[i][0];
        float2 p1 = *(float2*)&accA[i][1];
        float2 p2 = *(float2*)&accA[i][2];
        float2 p3 = *(float2*)&accA[i][3];
        float4 v0 = make_float4(p0.x + bias, p0.y + bias, p1.x + bias, p1.y + bias);
        float4 v1 = make_float4(p2.x + bias, p2.y + bias, p3.x + bias, p3.y + bias);
        float* dst = out + ((size_t)b * CO + co) * HW + prow + gpx * 8;
        *(float4*)dst       = v0;
        *(float4*)(dst + 4) = v1;
    }
}

// ---------------------------------------------------------------------------
extern "C" void kernel_launch(void* const* d_in, const int* in_sizes, int n_in,
                              void* d_out, int out_size) {
    const float* x     = (const float*)d_in[0];
    const float* w_off = (const float*)d_in[1];
    const float* b_off = (const float*)d_in[2];
    const float* w_dcn = (const float*)d_in[3];
    const float* b_dcn = (const float*)d_in[4];
    (void)in_sizes; (void)n_in; (void)out_size;

    int prepack_total = 9 * CI * CO * 2 + 9 * CI * OC * 2;
    k_prepack<<<(prepack_total + 127) / 128, 128>>>(w_dcn, w_off);
    k_transpose<<<dim3(HW / 32, CI / 32, BN), dim3(32, 8)>>>(x);
    k_offconv<<<BN * HW / 64, 128>>>(b_off);
    k_deform<<<BN * HW / 64, 128>>>(b_dcn, (float*)d_out);
}

// round 6
// speedup vs baseline: 1.2503x; 1.2503x over previous
#include <cuda_runtime.h>
#include <cstdint>

#define DEVFN __device__ __forceinline__

constexpr int BN = 16;      // batch
constexpr int CI = 64;      // in channels
constexpr int CO = 64;      // out channels
constexpr int HW = 4096;    // 64x64
constexpr int OC = 18;      // offset channels (2*K*K)
constexpr int OSTR = 20;    // g_off row stride (floats)

// Scratch (static device memory)
__device__ __align__(16) float g_xt [BN * HW * CI];       // x in NHWC
__device__ __align__(16) float g_off[BN * HW * OSTR];     // offsets [pixel][20]
__device__ __align__(16) float g_wt [9 * CI * CO];        // w_dcn [tap][cin][co] (non-dup)
__device__ __align__(16) float g_wo2[9 * CI * OC * 2];    // w_off dup: [((t*64+k)*18+oc)*2+d]
__device__ __align__(16) float4 g_cfw[BN * HW * 9];       // bilinear weights per (pix,tap)
__device__ __align__(16) int4   g_cfi[BN * HW * 9];       // clamped corner base offsets

DEVFN void fma2(unsigned long long& d, unsigned long long a, unsigned long long b) {
    asm("fma.rn.f32x2 %0, %1, %2, %0;" : "+l"(d) : "l"(a), "l"(b));
}
union F4U { float4 f; unsigned long long u[2]; };

// ---------------------------------------------------------------------------
// Weight prepack
// ---------------------------------------------------------------------------
__global__ void k_prepack(const float* __restrict__ wdcn, const float* __restrict__ woff) {
    int i = blockIdx.x * blockDim.x + threadIdx.x;
    if (i < 9 * CI * CO) {
        int co  = i & 63;
        int cin = (i >> 6) & 63;
        int t   = i >> 12;
        g_wt[i] = wdcn[(co * CI + cin) * 9 + t];
    }
    int j = i - 9 * CI * CO;
    if (j >= 0 && j < 9 * CI * OC * 2) {
        int r  = j >> 1;
        int oc = r % OC;
        int rk = r / OC;
        int k  = rk & 63;
        int t  = rk >> 6;
        g_wo2[j] = woff[(oc * CI + k) * 9 + t];
    }
}

// ---------------------------------------------------------------------------
// NCHW -> NHWC transpose
// ---------------------------------------------------------------------------
__global__ void k_transpose(const float* __restrict__ x) {
    __shared__ float s[32][33];
    int b  = blockIdx.z;
    int c0 = blockIdx.y * 32;
    int p0 = blockIdx.x * 32;
    int tx = threadIdx.x, ty = threadIdx.y;   // 32 x 8
    const float* xb = x + (size_t)b * CI * HW;
#pragma unroll
    for (int i = 0; i < 4; i++)
        s[ty + 8 * i][tx] = xb[(size_t)(c0 + ty + 8 * i) * HW + p0 + tx];
    __syncthreads();
    float* xtb = g_xt + (size_t)b * HW * CI;
#pragma unroll
    for (int i = 0; i < 4; i++)
        xtb[(size_t)(p0 + ty + 8 * i) * CI + c0 + tx] = s[tx][ty + 8 * i];
}

// ---------------------------------------------------------------------------
// Bilinear coefficient precompute: one item per (pixel, tap).
// Removes the x32-redundant per-lane coefficient math from k_deform's gather.
// ---------------------------------------------------------------------------
__global__ void k_coeff() {
    int i = blockIdx.x * blockDim.x + threadIdx.x;    // i = gpix*9 + t
    int gpix = i / 9;
    int t = i - gpix * 9;
    int ho = (gpix >> 6) & 63, wo = gpix & 63;
    float2 o2 = *(const float2*)(g_off + (size_t)gpix * OSTR + 2 * t);
    float py  = (float)(ho + t / 3 - 1) + o2.x;
    float pxx = (float)(wo + t % 3 - 1) + o2.y;
    float y0f = floorf(py), x0f = floorf(pxx);
    float fy = py - y0f, fx = pxx - x0f;
    int y0 = (int)y0f, x0 = (int)x0f;
    float vy0 = ((unsigned)y0 < 64u) ? 1.f : 0.f;
    float vy1 = ((unsigned)(y0 + 1) < 64u) ? 1.f : 0.f;
    float vx0 = ((unsigned)x0 < 64u) ? 1.f : 0.f;
    float vx1 = ((unsigned)(x0 + 1) < 64u) ? 1.f : 0.f;
    float gy0 = 1.f - fy, gx0 = 1.f - fx;
    g_cfw[i] = make_float4(gy0 * gx0 * vy0 * vx0, gy0 * fx * vy0 * vx1,
                           fy * gx0 * vy1 * vx0,  fy * fx * vy1 * vx1);
    int yc0 = min(max(y0, 0), 63),     yc1 = min(max(y0 + 1, 0), 63);
    int xc0 = min(max(x0, 0), 63),     xc1 = min(max(x0 + 1, 0), 63);
    g_cfi[i] = make_int4((((yc0 << 6) + xc0) << 6), (((yc0 << 6) + xc1) << 6),
                         (((yc1 << 6) + xc0) << 6), (((yc1 << 6) + xc1) << 6));
}

// Pair-major swizzled im2col cell: float4 = {v(2k2,p), v(2k2,p+1), v(2k2+1,p), v(2k2+1,p+1)}
// at colv[p2*32 + (k2 ^ ((p2>>2)&7))]. Conflict-free on both phases.

// ---------------------------------------------------------------------------
// Offset conv: 3x3, 64->18. Tile = 64 px (one row), 128 threads, grid 1024.
// Weights staged per tap in smem (pre-duplicated in gmem, tiny).
// ---------------------------------------------------------------------------
__global__ __launch_bounds__(128, 6) void k_offconv(const float* __restrict__ boff) {
    __shared__ __align__(16) float4 colv[32 * 32];    // 16 KB
    __shared__ __align__(16) float4 wos[CI * 9];      // 9.2 KB (dup tap weights)
    int tid  = threadIdx.x;
    int base = blockIdx.x * 64;
    int b    = base >> 12;
    int prow = base & 4095;
    int ho   = prow >> 6;
    const float* xtb = g_xt + (size_t)b * HW * CI;
    int lane = tid & 31, wrp = tid >> 5;
    int gco = tid >> 3, gpx = tid & 7;   // active for tid < 72 (gco < 9)

    unsigned long long acc[2][4];
#pragma unroll
    for (int i = 0; i < 2; i++)
#pragma unroll
        for (int j = 0; j < 4; j++) acc[i][j] = 0ULL;

    for (int t = 0; t < 9; t++) {
        // stage dup weights for this tap: 576 float4
        {
            const float4* s = ((const float4*)g_wo2) + t * 576;
#pragma unroll
            for (int r = 0; r < 5; r++) {
                int i = tid + 128 * r;
                if (i < 576) wos[i] = s[i];
            }
        }
        int dy = t / 3 - 1;
        int dx = t - (t / 3) * 3 - 1;
        int y  = ho + dy;
        bool yok = ((unsigned)y < 64u);
        // gather: 8 cells/thread (p2 = wrp*8+it), each = 2ch x 2px
#pragma unroll
        for (int it = 0; it < 8; it++) {
            int p2 = wrp * 8 + it;
            int q0 = 2 * p2;
            int x0p = q0 + dx, x1p = x0p + 1;
            float2 a = make_float2(0.f, 0.f), bb = make_float2(0.f, 0.f);
            if (yok && (unsigned)x0p < 64u)
                a = *((const float2*)(xtb + (((y << 6) + x0p) << 6)) + lane);
            if (yok && (unsigned)x1p < 64u)
                bb = *((const float2*)(xtb + (((y << 6) + x1p) << 6)) + lane);
            colv[p2 * 32 + (lane ^ ((p2 >> 2) & 7))] = make_float4(a.x, bb.x, a.y, bb.y);
        }
        __syncthreads();
        if (tid < 72) {
#pragma unroll 2
            for (int k2 = 0; k2 < 32; k2++) {
                F4U wE, wO;
                wE.f = wos[(2 * k2) * 9 + gco];       // {w(2k2,2gco)dup, w(2k2,2gco+1)dup}
                wO.f = wos[(2 * k2 + 1) * 9 + gco];
#pragma unroll
                for (int j = 0; j < 4; j++) {
                    F4U cv; cv.f = colv[(gpx * 4 + j) * 32 + (k2 ^ gpx)];
                    fma2(acc[0][j], wE.u[0], cv.u[0]); fma2(acc[0][j], wO.u[0], cv.u[1]);
                    fma2(acc[1][j], wE.u[1], cv.u[0]); fma2(acc[1][j], wO.u[1], cv.u[1]);
                }
            }
        }
        __syncthreads();
    }
    if (tid < 72) {
        int co0 = 2 * gco;
#pragma unroll
        for (int i = 0; i < 2; i++) {
            float bo = boff[co0 + i];
#pragma unroll
            for (int j = 0; j < 4; j++) {
                float2 p = *(float2*)&acc[i][j];
                int px = gpx * 8 + 2 * j;
                g_off[(size_t)(base + px)     * OSTR + co0 + i] = p.x + bo;
                g_off[(size_t)(base + px + 1) * OSTR + co0 + i] = p.y + bo;
            }
        }
    }
}

// ---------------------------------------------------------------------------
// Deformable conv. Tile = 64 px x 64 co, 128 threads, grid 1024.
// Gather uses precomputed coeffs; GEMM uses smem-staged duplicated weights
// (half-tap = 16 KB at a time; duplication done during the smem store).
// ---------------------------------------------------------------------------
__global__ __launch_bounds__(128, 6) void k_deform(const float* __restrict__ bdcn,
                                                   float* __restrict__ out) {
    __shared__ __align__(16) float4 colv[32 * 32];    // 16 KB
    __shared__ __align__(16) float4 ws4[32 * 32];     // 16 KB (half-tap, dup)
    int tid  = threadIdx.x;
    int base = blockIdx.x * 64;
    int b    = base >> 12;
    int prow = base & 4095;
    const float* xtb = g_xt + (size_t)b * HW * CI;
    int lane = tid & 31, wrp = tid >> 5;
    int gco = tid >> 3, gpx = tid & 7;
    int co0 = 4 * gco;

    unsigned long long acc[4][4];
#pragma unroll
    for (int i = 0; i < 4; i++)
#pragma unroll
        for (int j = 0; j < 4; j++) acc[i][j] = 0ULL;

    for (int t = 0; t < 9; t++) {
        // ---- stage half0 weights (k 0..31), duplicating on store ----
        {
            const float4* s = ((const float4*)g_wt) + (t * 64) * 16;
#pragma unroll
            for (int r = 0; r < 4; r++) {
                int i = tid + 128 * r;
                float4 v = s[i];
                int k = i >> 4, c4 = i & 15;
                ws4[k * 32 + 2 * c4]     = make_float4(v.x, v.x, v.y, v.y);
                ws4[k * 32 + 2 * c4 + 1] = make_float4(v.z, v.z, v.w, v.w);
            }
        }
        // ---- gather with precomputed coeffs: 8 cells/thread ----
#pragma unroll 2
        for (int it = 0; it < 8; it++) {
            int p2 = wrp * 8 + it;
            int q0 = 2 * p2;
            int cbase = (base + q0) * 9 + t;
            float4 cw0 = g_cfw[cbase];     int4 ii0 = g_cfi[cbase];
            float4 cw1 = g_cfw[cbase + 9]; int4 ii1 = g_cfi[cbase + 9];
            float2 r0, r1;
            {
                float2 v00 = *((const float2*)(xtb + ii0.x) + lane);
                float2 v01 = *((const float2*)(xtb + ii0.y) + lane);
                float2 v10 = *((const float2*)(xtb + ii0.z) + lane);
                float2 v11 = *((const float2*)(xtb + ii0.w) + lane);
                r0.x = cw0.x * v00.x + cw0.y * v01.x + cw0.z * v10.x + cw0.w * v11.x;
                r0.y = cw0.x * v00.y + cw0.y * v01.y + cw0.z * v10.y + cw0.w * v11.y;
            }
            {
                float2 v00 = *((const float2*)(xtb + ii1.x) + lane);
                float2 v01 = *((const float2*)(xtb + ii1.y) + lane);
                float2 v10 = *((const float2*)(xtb + ii1.z) + lane);
                float2 v11 = *((const float2*)(xtb + ii1.w) + lane);
                r1.x = cw1.x * v00.x + cw1.y * v01.x + cw1.z * v10.x + cw1.w * v11.x;
                r1.y = cw1.x * v00.y + cw1.y * v01.y + cw1.z * v10.y + cw1.w * v11.y;
            }
            colv[p2 * 32 + (lane ^ ((p2 >> 2) & 7))] = make_float4(r0.x, r1.x, r0.y, r1.y);
        }
        __syncthreads();
        // ---- GEMM: two 32-k halves ----
#pragma unroll 1
        for (int h = 0; h < 2; h++) {
#pragma unroll 2
            for (int l2 = 0; l2 < 16; l2++) {
                int kA = 2 * l2, kB = 2 * l2 + 1;
                F4U wE0, wE1, wO0, wO1;
                wE0.f = ws4[kA * 32 + 2 * gco];     // co0,co0+1 dup (k even)
                wE1.f = ws4[kA * 32 + 2 * gco + 1]; // co0+2,co0+3 dup
                wO0.f = ws4[kB * 32 + 2 * gco];     // (k odd)
                wO1.f = ws4[kB * 32 + 2 * gco + 1];
                int k2g = 16 * h + l2;
#pragma unroll
                for (int j = 0; j < 4; j++) {
                    F4U cv; cv.f = colv[(gpx * 4 + j) * 32 + (k2g ^ gpx)];
                    fma2(acc[0][j], wE0.u[0], cv.u[0]); fma2(acc[0][j], wO0.u[0], cv.u[1]);
                    fma2(acc[1][j], wE0.u[1], cv.u[0]); fma2(acc[1][j], wO0.u[1], cv.u[1]);
                    fma2(acc[2][j], wE1.u[0], cv.u[0]); fma2(acc[2][j], wO1.u[0], cv.u[1]);
                    fma2(acc[3][j], wE1.u[1], cv.u[0]); fma2(acc[3][j], wO1.u[1], cv.u[1]);
                }
            }
            __syncthreads();
            if (h == 0) {   // stage half1 (k 32..63)
                const float4* s = ((const float4*)g_wt) + (t * 64 + 32) * 16;
#pragma unroll
                for (int r = 0; r < 4; r++) {
                    int i = tid + 128 * r;
                    float4 v = s[i];
                    int k = i >> 4, c4 = i & 15;
                    ws4[k * 32 + 2 * c4]     = make_float4(v.x, v.x, v.y, v.y);
                    ws4[k * 32 + 2 * c4 + 1] = make_float4(v.z, v.z, v.w, v.w);
                }
                __syncthreads();
            }
        }
    }
    // ---- epilogue: out[b][co][row][px] (NCHW) ----
#pragma unroll
    for (int i = 0; i < 4; i++) {
        int co = co0 + i;
        float bias = bdcn[co];
        float2 p0 = *(float2*)&acc[i][0];
        float2 p1 = *(float2*)&acc[i][1];
        float2 p2 = *(float2*)&acc[i][2];
        float2 p3 = *(float2*)&acc[i][3];
        float4 v0 = make_float4(p0.x + bias, p0.y + bias, p1.x + bias, p1.y + bias);
        float4 v1 = make_float4(p2.x + bias, p2.y + bias, p3.x + bias, p3.y + bias);
        float* dst = out + ((size_t)b * CO + co) * HW + prow + gpx * 8;
        *(float4*)dst       = v0;
        *(float4*)(dst + 4) = v1;
    }
}

// ---------------------------------------------------------------------------
extern "C" void kernel_launch(void* const* d_in, const int* in_sizes, int n_in,
                              void* d_out, int out_size) {
    const float* x     = (const float*)d_in[0];
    const float* w_off = (const float*)d_in[1];
    const float* b_off = (const float*)d_in[2];
    const float* w_dcn = (const float*)d_in[3];
    const float* b_dcn = (const float*)d_in[4];
    (void)in_sizes; (void)n_in; (void)out_size;

    int prepack_total = 9 * CI * CO + 9 * CI * OC * 2;
    k_prepack<<<(prepack_total + 127) / 128, 128>>>(w_dcn, w_off);
    k_transpose<<<dim3(HW / 32, CI / 32, BN), dim3(32, 8)>>>(x);
    k_offconv<<<BN * HW / 64, 128>>>(b_off);
    k_coeff<<<BN * HW * 9 / 128, 128>>>();
    k_deform<<<BN * HW / 64, 128>>>(b_dcn, (float*)d_out);
}

// round 12
// speedup vs baseline: 1.6802x; 1.3439x over previous
#include <cuda_runtime.h>
#include <cuda_bf16.h>
#include <cstdint>

#define DEVFN __device__ __forceinline__

constexpr int BN = 16;      // batch
constexpr int CI = 64;      // in channels
constexpr int CO = 64;      // out channels
constexpr int HW = 4096;    // 64x64
constexpr int OC = 18;      // offset channels
constexpr int OSTR = 20;    // g_off row stride (floats)

// Scratch (static device memory)
__device__ __align__(16) float g_xt [BN * HW * CI];       // x in NHWC
__device__ __align__(16) float g_off[BN * HW * OSTR];     // offsets [pixel][20]
__device__ __align__(16) float g_wo2[9 * CI * OC * 2];    // offconv weights dup
__device__ __align__(16) __nv_bfloat16 g_wbh[9 * 4096];   // w_dcn hi, per-tap SW128-swizzled [co][cin]
__device__ __align__(16) __nv_bfloat16 g_wbl[9 * 4096];   // w_dcn lo
__device__ __align__(16) float4 g_cfw[BN * HW * 9];       // bilinear weights per (pix,tap)
__device__ __align__(16) int4   g_cfi[BN * HW * 9];       // clamped corner base offsets

DEVFN void fma2(unsigned long long& d, unsigned long long a, unsigned long long b) {
    asm("fma.rn.f32x2 %0, %1, %2, %0;" : "+l"(d) : "l"(a), "l"(b));
}
union F4U { float4 f; unsigned long long u[2]; };

DEVFN uint32_t smem_u32(const void* p) {
    uint32_t a;
    asm("{ .reg .u64 t; cvta.to.shared.u64 t, %1; cvt.u32.u64 %0, t; }" : "=r"(a) : "l"(p));
    return a;
}
// ---- ldmatrix / mma.sync (sm_80+ PTX, valid on plain sm_103 target) ----
DEVFN void ldm_x4(uint32_t* r, uint32_t addr) {
    asm volatile("ldmatrix.sync.aligned.m8n8.x4.shared.b16 {%0,%1,%2,%3}, [%4];"
                 : "=r"(r[0]), "=r"(r[1]), "=r"(r[2]), "=r"(r[3]) : "r"(addr));
}
DEVFN void ldm_x2(uint32_t* r, uint32_t addr) {
    asm volatile("ldmatrix.sync.aligned.m8n8.x2.shared.b16 {%0,%1}, [%2];"
                 : "=r"(r[0]), "=r"(r[1]) : "r"(addr));
}
DEVFN void mma_bf16(float* d, const uint32_t* a, const uint32_t* b) {
    asm volatile("mma.sync.aligned.m16n8k16.row.col.f32.bf16.bf16.f32 "
                 "{%0,%1,%2,%3}, {%4,%5,%6,%7}, {%8,%9}, {%0,%1,%2,%3};"
                 : "+f"(d[0]), "+f"(d[1]), "+f"(d[2]), "+f"(d[3])
                 : "r"(a[0]), "r"(a[1]), "r"(a[2]), "r"(a[3]), "r"(b[0]), "r"(b[1]));
}
DEVFN uint32_t sw128(uint32_t byte) { return byte ^ ((byte >> 3) & 0x70); }

// ---------------------------------------------------------------------------
// Weight prepack: bf16 hi/lo split + SW128 pre-swizzle for dcn (B = [co][cin]
// rows of 128 B), duplicated fp32 for offconv.
// ---------------------------------------------------------------------------
__global__ void k_prepack(const float* __restrict__ wdcn, const float* __restrict__ woff) {
    int i = blockIdx.x * blockDim.x + threadIdx.x;
    if (i < 9 * 4096) {
        int t = i >> 12, r = i & 4095;
        int co = r >> 6, cin = r & 63;
        float w = wdcn[(co * CI + cin) * 9 + t];
        __nv_bfloat16 hi = __float2bfloat16(w);
        __nv_bfloat16 lo = __float2bfloat16(w - __bfloat162float(hi));
        uint32_t sw = sw128((uint32_t)(co * 128 + cin * 2));
        g_wbh[t * 4096 + (sw >> 1)] = hi;
        g_wbl[t * 4096 + (sw >> 1)] = lo;
    }
    int j = i - 9 * 4096;
    if (j >= 0 && j < 9 * CI * OC * 2) {
        int r  = j >> 1;
        int oc = r % OC;
        int rk = r / OC;
        int k  = rk & 63;
        int t  = rk >> 6;
        g_wo2[j] = woff[(oc * CI + k) * 9 + t];
    }
}

// ---------------------------------------------------------------------------
// NCHW -> NHWC transpose
// ---------------------------------------------------------------------------
__global__ void k_transpose(const float* __restrict__ x) {
    __shared__ float s[32][33];
    int b  = blockIdx.z;
    int c0 = blockIdx.y * 32;
    int p0 = blockIdx.x * 32;
    int tx = threadIdx.x, ty = threadIdx.y;
    const float* xb = x + (size_t)b * CI * HW;
#pragma unroll
    for (int i = 0; i < 4; i++)
        s[ty + 8 * i][tx] = xb[(size_t)(c0 + ty + 8 * i) * HW + p0 + tx];
    __syncthreads();
    float* xtb = g_xt + (size_t)b * HW * CI;
#pragma unroll
    for (int i = 0; i < 4; i++)
        xtb[(size_t)(p0 + ty + 8 * i) * CI + c0 + tx] = s[tx][ty + 8 * i];
}

// ---------------------------------------------------------------------------
// Bilinear coefficient precompute (per pixel, tap)
// ---------------------------------------------------------------------------
__global__ void k_coeff() {
    int i = blockIdx.x * blockDim.x + threadIdx.x;
    int gpix = i / 9;
    int t = i - gpix * 9;
    int ho = (gpix >> 6) & 63, wo = gpix & 63;
    float2 o2 = *(const float2*)(g_off + (size_t)gpix * OSTR + 2 * t);
    float py  = (float)(ho + t / 3 - 1) + o2.x;
    float pxx = (float)(wo + t % 3 - 1) + o2.y;
    float y0f = floorf(py), x0f = floorf(pxx);
    float fy = py - y0f, fx = pxx - x0f;
    int y0 = (int)y0f, x0 = (int)x0f;
    float vy0 = ((unsigned)y0 < 64u) ? 1.f : 0.f;
    float vy1 = ((unsigned)(y0 + 1) < 64u) ? 1.f : 0.f;
    float vx0 = ((unsigned)x0 < 64u) ? 1.f : 0.f;
    float vx1 = ((unsigned)(x0 + 1) < 64u) ? 1.f : 0.f;
    float gy0 = 1.f - fy, gx0 = 1.f - fx;
    g_cfw[i] = make_float4(gy0 * gx0 * vy0 * vx0, gy0 * fx * vy0 * vx1,
                           fy * gx0 * vy1 * vx0,  fy * fx * vy1 * vx1);
    int yc0 = min(max(y0, 0), 63),     yc1 = min(max(y0 + 1, 0), 63);
    int xc0 = min(max(x0, 0), 63),     xc1 = min(max(x0 + 1, 0), 63);
    g_cfi[i] = make_int4((((yc0 << 6) + xc0) << 6), (((yc0 << 6) + xc1) << 6),
                         (((yc1 << 6) + xc0) << 6), (((yc1 << 6) + xc1) << 6));
}

// ---------------------------------------------------------------------------
// Offset conv (SIMT f32x2 — unchanged, small fraction of runtime)
// ---------------------------------------------------------------------------
__global__ __launch_bounds__(128, 6) void k_offconv(const float* __restrict__ boff) {
    __shared__ __align__(16) float4 colv[32 * 32];
    __shared__ __align__(16) float4 wos[CI * 9];
    int tid  = threadIdx.x;
    int base = blockIdx.x * 64;
    int b    = base >> 12;
    int prow = base & 4095;
    int ho   = prow >> 6;
    const float* xtb = g_xt + (size_t)b * HW * CI;
    int lane = tid & 31, wrp = tid >> 5;
    int gco = tid >> 3, gpx = tid & 7;

    unsigned long long acc[2][4];
#pragma unroll
    for (int i = 0; i < 2; i++)
#pragma unroll
        for (int j = 0; j < 4; j++) acc[i][j] = 0ULL;

    for (int t = 0; t < 9; t++) {
        {
            const float4* s = ((const float4*)g_wo2) + t * 576;
#pragma unroll
            for (int r = 0; r < 5; r++) {
                int i = tid + 128 * r;
                if (i < 576) wos[i] = s[i];
            }
        }
        int dy = t / 3 - 1;
        int dx = t - (t / 3) * 3 - 1;
        int y  = ho + dy;
        bool yok = ((unsigned)y < 64u);
#pragma unroll
        for (int it = 0; it < 8; it++) {
            int p2 = wrp * 8 + it;
            int q0 = 2 * p2;
            int x0p = q0 + dx, x1p = x0p + 1;
            float2 a = make_float2(0.f, 0.f), bb = make_float2(0.f, 0.f);
            if (yok && (unsigned)x0p < 64u)
                a = *((const float2*)(xtb + (((y << 6) + x0p) << 6)) + lane);
            if (yok && (unsigned)x1p < 64u)
                bb = *((const float2*)(xtb + (((y << 6) + x1p) << 6)) + lane);
            colv[p2 * 32 + (lane ^ ((p2 >> 2) & 7))] = make_float4(a.x, bb.x, a.y, bb.y);
        }
        __syncthreads();
        if (tid < 72) {
#pragma unroll 2
            for (int k2 = 0; k2 < 32; k2++) {
                F4U wE, wO;
                wE.f = wos[(2 * k2) * 9 + gco];
                wO.f = wos[(2 * k2 + 1) * 9 + gco];
#pragma unroll
                for (int j = 0; j < 4; j++) {
                    F4U cv; cv.f = colv[(gpx * 4 + j) * 32 + (k2 ^ gpx)];
                    fma2(acc[0][j], wE.u[0], cv.u[0]); fma2(acc[0][j], wO.u[0], cv.u[1]);
                    fma2(acc[1][j], wE.u[1], cv.u[0]); fma2(acc[1][j], wO.u[1], cv.u[1]);
                }
            }
        }
        __syncthreads();
    }
    if (tid < 72) {
        int co0 = 2 * gco;
#pragma unroll
        for (int i = 0; i < 2; i++) {
            float bo = boff[co0 + i];
#pragma unroll
            for (int j = 0; j < 4; j++) {
                float2 p = *(float2*)&acc[i][j];
                int px = gpx * 8 + 2 * j;
                g_off[(size_t)(base + px)     * OSTR + co0 + i] = p.x + bo;
                g_off[(size_t)(base + px + 1) * OSTR + co0 + i] = p.y + bo;
            }
        }
    }
}

// ---------------------------------------------------------------------------
// Deformable conv: split-bf16 mma.sync GEMM. CTA = 256 thr, 128 px x 64 co.
// Per tap: gather -> swizzled bf16 A hi/lo; B hi/lo pre-swizzled copy; 8 warps
// x (32px x 32co) warp tiles; 3 split passes share fp32 accumulators.
// smem: Ah[0,16K) Al[16K,32K) Bh[32K,40K) Bl[40K,48K); reused for epilogue.
// ---------------------------------------------------------------------------
__global__ __launch_bounds__(256) void k_deform(const float* __restrict__ bdcn,
                                                float* __restrict__ out) {
    __shared__ __align__(128) char smem[49152];
    uint32_t sb = smem_u32(smem);
    int tid = threadIdx.x, wid = tid >> 5, lane = tid & 31;
    int base = blockIdx.x * 128;
    int b    = base >> 12;
    int prow = base & 4095;
    const float* xtb = g_xt + (size_t)b * HW * CI;
    int wm = wid >> 1, wn = wid & 1;          // warp grid 4(m) x 2(n)
    int mbase = wm * 32, nbase = wn * 32;

    float acc[2][4][4];
#pragma unroll
    for (int mi = 0; mi < 2; mi++)
#pragma unroll
        for (int ni = 0; ni < 4; ni++)
#pragma unroll
            for (int e = 0; e < 4; e++) acc[mi][ni][e] = 0.f;

    for (int t = 0; t < 9; t++) {
        // ---- stage B hi/lo (pre-swizzled; straight copy of 512+512 uint4) ----
        {
            const uint4* sh = (const uint4*)(g_wbh + t * 4096);
            const uint4* sl = (const uint4*)(g_wbl + t * 4096);
            ((uint4*)(smem + 32768))[tid]       = sh[tid];
            ((uint4*)(smem + 32768))[tid + 256] = sh[tid + 256];
            ((uint4*)(smem + 40960))[tid]       = sl[tid];
            ((uint4*)(smem + 40960))[tid + 256] = sl[tid + 256];
        }
        // ---- gather: warp w handles pixels w*16..w*16+15, lane = ch-pair ----
#pragma unroll 2
        for (int i = 0; i < 16; i++) {
            int p = wid * 16 + i;
            int ci = (base + p) * 9 + t;
            float4 cw = g_cfw[ci];
            int4  ii = g_cfi[ci];
            float2 v00 = *((const float2*)(xtb + ii.x) + lane);
            float2 v01 = *((const float2*)(xtb + ii.y) + lane);
            float2 v10 = *((const float2*)(xtb + ii.z) + lane);
            float2 v11 = *((const float2*)(xtb + ii.w) + lane);
            float2 v;
            v.x = cw.x * v00.x + cw.y * v01.x + cw.z * v10.x + cw.w * v11.x;
            v.y = cw.x * v00.y + cw.y * v01.y + cw.z * v10.y + cw.w * v11.y;
            __nv_bfloat162 h2 = __float22bfloat162_rn(v);
            float2 fh = __bfloat1622float2(h2);
            __nv_bfloat162 l2 = __float22bfloat162_rn(make_float2(v.x - fh.x, v.y - fh.y));
            uint32_t sw = sw128((uint32_t)(p * 128 + lane * 4));
            *(uint32_t*)(smem + sw)         = *(uint32_t*)&h2;   // A_hi
            *(uint32_t*)(smem + 16384 + sw) = *(uint32_t*)&l2;   // A_lo
        }
        __syncthreads();
        // ---- warp GEMM: 4 k16 chunks, 3 split passes on shared accumulators ----
#pragma unroll
        for (int k16 = 0; k16 < 4; k16++) {
            uint32_t ah[2][4], al[2][4];
#pragma unroll
            for (int mi = 0; mi < 2; mi++) {
                int row = mbase + mi * 16 + (lane & 15);
                uint32_t byte = sw128((uint32_t)(row * 128 + k16 * 32 + ((lane >> 4) << 4)));
                ldm_x4(ah[mi], sb + byte);
                ldm_x4(al[mi], sb + 16384 + byte);
            }
            uint32_t bh[4][2], bl[4][2];
#pragma unroll
            for (int ni = 0; ni < 4; ni++) {
                int n = nbase + ni * 8 + (lane & 7);
                uint32_t byte = sw128((uint32_t)(n * 128 + k16 * 32 + (((lane >> 3) & 1) << 4)));
                ldm_x2(bh[ni], sb + 32768 + byte);
                ldm_x2(bl[ni], sb + 40960 + byte);
            }
#pragma unroll
            for (int mi = 0; mi < 2; mi++)
#pragma unroll
                for (int ni = 0; ni < 4; ni++) {
                    mma_bf16(acc[mi][ni], ah[mi], bh[ni]);
                    mma_bf16(acc[mi][ni], al[mi], bh[ni]);
                    mma_bf16(acc[mi][ni], ah[mi], bl[ni]);
                }
        }
        __syncthreads();
    }
    // ---- epilogue: bounce acc through smem [co][132] for coalesced stores ----
    float* sAcc = (float*)smem;
    int r = lane >> 2, g = lane & 3;
#pragma unroll
    for (int mi = 0; mi < 2; mi++)
#pragma unroll
        for (int ni = 0; ni < 4; ni++) {
            int co = nbase + ni * 8 + g * 2;
            int px = mbase + mi * 16 + r;
            sAcc[co * 132 + px]             = acc[mi][ni][0];
            sAcc[(co + 1) * 132 + px]       = acc[mi][ni][1];
            sAcc[co * 132 + px + 8]         = acc[mi][ni][2];
            sAcc[(co + 1) * 132 + px + 8]   = acc[mi][ni][3];
        }
    __syncthreads();
    float* ob = out + (size_t)b * CO * HW + prow;
#pragma unroll
    for (int it = 0; it < 8; it++) {
        int idx = tid + 256 * it;          // 2048 float4 total
        int row = idx >> 5, c4 = idx & 31;
        float4 v = *(float4*)(sAcc + row * 132 + c4 * 4);
        float bias = bdcn[row];
        v.x += bias; v.y += bias; v.z += bias; v.w += bias;
        *(float4*)(ob + (size_t)row * HW + c4 * 4) = v;
    }
}

// ---------------------------------------------------------------------------
extern "C" void kernel_launch(void* const* d_in, const int* in_sizes, int n_in,
                              void* d_out, int out_size) {
    const float* x     = (const float*)d_in[0];
    const float* w_off = (const float*)d_in[1];
    const float* b_off = (const float*)d_in[2];
    const float* w_dcn = (const float*)d_in[3];
    const float* b_dcn = (const float*)d_in[4];
    (void)in_sizes; (void)n_in; (void)out_size;

    int prepack_total = 9 * 4096 + 9 * CI * OC * 2;
    k_prepack<<<(prepack_total + 127) / 128, 128>>>(w_dcn, w_off);
    k_transpose<<<dim3(HW / 32, CI / 32, BN), dim3(32, 8)>>>(x);
    k_offconv<<<BN * HW / 64, 128>>>(b_off);
    k_coeff<<<BN * HW * 9 / 128, 128>>>();
    k_deform<<<BN * HW / 128, 256>>>(b_dcn, (float*)d_out);
}